// round 3
// baseline (speedup 1.0000x reference)
#include <cuda_runtime.h>

// Problem constants (fixed by the dataset)
#define NN    50000
#define EE    800000
#define INDIM 64
#define HID   256
#define OUTD  128
#define C2    512   // 2*HID

// ---------------- device scratch (static: no allocation allowed) ----------------
__device__ float g_x3 [NN * C2];     // [N,512]  = concat(x1, x2)
__device__ float g_xc1[NN * HID];    // x @ w_conv1 (raw)
__device__ float g_xc2[NN * OUTD];   // x3 @ w_conv2 (raw)
__device__ float g_x7 [NN * OUTD];   // x5 then x5+x6
__device__ float g_xc3[NN];          // x7 @ w_conv3 (raw)
__device__ float g_pre[NN];          // x7 @ w_fc2 + b_fc2
__device__ float g_dis[NN];          // deg^-1/2 (0 if deg==0)
__device__ int   g_deg[NN];
__device__ int   g_colptr[NN + 1];
__device__ int   g_cursor[NN];
__device__ int   g_erow[EE];         // source row per CSR slot (sorted by dest col)
__device__ float g_ewt [EE];         // dis[row] per CSR slot
__device__ int   g_bsum[1024];
__device__ int   g_is64;

// ---------------- edge dtype handling ----------------
// Reference declares edge_index as int64, but JAX without x64 emits int32.
// Detect: values are in [0, 50000) so if data is int64, every odd int32 word is 0.
__global__ void detect_kernel(const int* __restrict__ p, int nwords) {
    __shared__ int any;
    if (threadIdx.x == 0) any = 0;
    __syncthreads();
    int v = 0;
    for (int i = threadIdx.x; i < nwords; i += blockDim.x)
        if (i & 1) v |= p[i];
    if (v) atomicOr(&any, 1);
    __syncthreads();
    if (threadIdx.x == 0) g_is64 = (any == 0) ? 1 : 0;
}

__device__ __forceinline__ int edge_val(const void* e, long idx) {
    if (g_is64) return (int)((const long long*)e)[idx];
    return ((const int*)e)[idx];
}

// ---------------- CSR build ----------------
__global__ void zero_deg_kernel(int n) {
    int i = blockIdx.x * blockDim.x + threadIdx.x;
    if (i < n) g_deg[i] = 0;
}

__global__ void count_kernel(const void* __restrict__ edges, int E) {
    int e = blockIdx.x * blockDim.x + threadIdx.x;
    if (e < E) {
        int c = edge_val(edges, (long)E + e);
        atomicAdd(&g_deg[c], 1);
    }
}

#define SCB 512
__global__ void scan_blocks_kernel(int n) {
    __shared__ int sm[SCB];
    int i = blockIdx.x * SCB + threadIdx.x;
    int v = (i < n) ? g_deg[i] : 0;
    sm[threadIdx.x] = v;
    __syncthreads();
    for (int off = 1; off < SCB; off <<= 1) {
        int t = 0;
        if ((int)threadIdx.x >= off) t = sm[threadIdx.x - off];
        __syncthreads();
        sm[threadIdx.x] += t;
        __syncthreads();
    }
    if (i < n) g_colptr[i] = sm[threadIdx.x] - v;     // exclusive within block
    if (threadIdx.x == SCB - 1) g_bsum[blockIdx.x] = sm[SCB - 1];
}

__global__ void scan_sums_kernel(int nb) {
    __shared__ int sm[1024];
    int v = (threadIdx.x < (unsigned)nb) ? g_bsum[threadIdx.x] : 0;
    sm[threadIdx.x] = v;
    __syncthreads();
    for (int off = 1; off < 1024; off <<= 1) {
        int t = 0;
        if ((int)threadIdx.x >= off) t = sm[threadIdx.x - off];
        __syncthreads();
        sm[threadIdx.x] += t;
        __syncthreads();
    }
    if (threadIdx.x < (unsigned)nb) g_bsum[threadIdx.x] = sm[threadIdx.x] - v;  // exclusive
}

__global__ void scan_add_kernel(int n, int Etot) {
    int i = blockIdx.x * SCB + threadIdx.x;
    if (i < n) {
        int v = g_colptr[i] + g_bsum[blockIdx.x];
        g_colptr[i] = v;
        g_cursor[i] = v;
    }
    if (i == 0) g_colptr[n] = Etot;
}

__global__ void dis_kernel(int n) {
    int i = blockIdx.x * blockDim.x + threadIdx.x;
    if (i < n) {
        int d = g_deg[i];
        g_dis[i] = (d > 0) ? rsqrtf((float)d) : 0.0f;
    }
}

__global__ void fill_kernel(const void* __restrict__ edges, int E) {
    int e = blockIdx.x * blockDim.x + threadIdx.x;
    if (e < E) {
        int r = edge_val(edges, e);
        int c = edge_val(edges, (long)E + e);
        int pos = atomicAdd(&g_cursor[c], 1);
        g_erow[pos] = r;
        g_ewt[pos]  = g_dis[r];
    }
}

// ---------------- GEMM 1: [N,64] @ [64, 512] (cols 0..255 -> relu+b_fc -> x3[:, :256],
//                                   cols 256..511 -> raw -> g_xc1) ----------------
__global__ __launch_bounds__(256) void gemm1_kernel(
    const float* __restrict__ x, const float* __restrict__ w_fc,
    const float* __restrict__ b_fc, const float* __restrict__ w_conv1, int n)
{
    __shared__ __align__(16) float As[128 * 64];
    __shared__ __align__(16) float Bs[64 * 64];
    int bm0 = blockIdx.x * 128;
    int bn0 = blockIdx.y * 64;
    bool isfc = (bn0 < 256);
    const float* B = isfc ? (w_fc + bn0) : (w_conv1 + (bn0 - 256));  // ldb = 256
    int tid = threadIdx.x;

    // load A tile 128x64 (2048 float4)
    #pragma unroll
    for (int i = 0; i < 8; i++) {
        int f = tid + i * 256;
        int r = f >> 4, c4 = f & 15;
        float4 v = make_float4(0.f, 0.f, 0.f, 0.f);
        if (bm0 + r < n) v = ((const float4*)x)[(long)(bm0 + r) * 16 + c4];
        ((float4*)As)[f] = v;
    }
    // load B tile 64x64 (1024 float4)
    #pragma unroll
    for (int i = 0; i < 4; i++) {
        int f = tid + i * 256;
        int r = f >> 4, c4 = f & 15;
        ((float4*)Bs)[f] = *(const float4*)(B + r * 256 + c4 * 4);
    }
    __syncthreads();

    int ty = tid >> 4, tx = tid & 15;
    float acc[8][4];
    #pragma unroll
    for (int r = 0; r < 8; r++)
        #pragma unroll
        for (int c = 0; c < 4; c++) acc[r][c] = 0.f;

    #pragma unroll
    for (int k = 0; k < 64; k++) {
        float4 bv = *(float4*)(Bs + k * 64 + tx * 4);
        #pragma unroll
        for (int r = 0; r < 8; r++) {
            float a = As[(ty * 8 + r) * 64 + k];
            acc[r][0] += a * bv.x; acc[r][1] += a * bv.y;
            acc[r][2] += a * bv.z; acc[r][3] += a * bv.w;
        }
    }

    int col = bn0 + tx * 4;
    #pragma unroll
    for (int r = 0; r < 8; r++) {
        int row = bm0 + ty * 8 + r;
        if (row >= n) continue;
        if (isfc) {
            float4 bb = *(const float4*)(b_fc + col);
            float4 o;
            o.x = fmaxf(acc[r][0] + bb.x, 0.f);
            o.y = fmaxf(acc[r][1] + bb.y, 0.f);
            o.z = fmaxf(acc[r][2] + bb.z, 0.f);
            o.w = fmaxf(acc[r][3] + bb.w, 0.f);
            *(float4*)(g_x3 + (long)row * C2 + col) = o;
        } else {
            float4 o = make_float4(acc[r][0], acc[r][1], acc[r][2], acc[r][3]);
            *(float4*)(g_xc1 + (long)row * HID + (col - 256)) = o;
        }
    }
}

// ---------------- Aggregate conv1: x3[:, 256:512] = relu(dis[i]*sum + b_conv1) ----------------
__global__ __launch_bounds__(256) void agg1_kernel(const float* __restrict__ b_conv1, int n) {
    int i = blockIdx.x;
    if (i >= n) return;
    int f = threadIdx.x;                 // 256
    int s = g_colptr[i], e = g_colptr[i + 1];
    float acc = 0.f;
    for (int p = s; p < e; p++) {
        int r   = g_erow[p];
        float w = g_ewt[p];
        acc += w * g_xc1[(long)r * HID + f];
    }
    float v = fmaxf(acc * g_dis[i] + b_conv1[f], 0.f);
    g_x3[(long)i * C2 + 256 + f] = v;
}

// ---------------- GEMM 2: [N,512] @ [512, 256] (cols 0..127 -> relu+b_fc1 -> g_x7,
//                                    cols 128..255 -> raw -> g_xc2) ----------------
__global__ __launch_bounds__(256) void gemm2_kernel(
    const float* __restrict__ w_fc1, const float* __restrict__ b_fc1,
    const float* __restrict__ w_conv2, int n)
{
    __shared__ __align__(16) float As[128 * 32];
    __shared__ __align__(16) float Bs[32 * 64];
    int bm0 = blockIdx.x * 128;
    int bn0 = blockIdx.y * 64;
    bool isfc = (bn0 < 128);
    const float* B = isfc ? (w_fc1 + bn0) : (w_conv2 + (bn0 - 128));  // ldb = 128
    const float* A = g_x3;
    int tid = threadIdx.x, ty = tid >> 4, tx = tid & 15;

    float acc[8][4];
    #pragma unroll
    for (int r = 0; r < 8; r++)
        #pragma unroll
        for (int c = 0; c < 4; c++) acc[r][c] = 0.f;

    for (int k0 = 0; k0 < 512; k0 += 32) {
        // load A tile 128x32 (1024 float4)
        #pragma unroll
        for (int i = 0; i < 4; i++) {
            int f = tid + i * 256;
            int r = f >> 3, c4 = f & 7;
            float4 v = make_float4(0.f, 0.f, 0.f, 0.f);
            if (bm0 + r < n) v = ((const float4*)A)[(long)(bm0 + r) * 128 + (k0 >> 2) + c4];
            ((float4*)As)[f] = v;
        }
        // load B tile 32x64 (512 float4)
        #pragma unroll
        for (int i = 0; i < 2; i++) {
            int f = tid + i * 256;
            int r = f >> 4, c4 = f & 15;
            ((float4*)Bs)[f] = *(const float4*)(B + (k0 + r) * 128 + c4 * 4);
        }
        __syncthreads();
        #pragma unroll
        for (int k = 0; k < 32; k++) {
            float4 bv = *(float4*)(Bs + k * 64 + tx * 4);
            #pragma unroll
            for (int r = 0; r < 8; r++) {
                float a = As[(ty * 8 + r) * 32 + k];
                acc[r][0] += a * bv.x; acc[r][1] += a * bv.y;
                acc[r][2] += a * bv.z; acc[r][3] += a * bv.w;
            }
        }
        __syncthreads();
    }

    int col = bn0 + tx * 4;
    #pragma unroll
    for (int r = 0; r < 8; r++) {
        int row = bm0 + ty * 8 + r;
        if (row >= n) continue;
        if (isfc) {
            float4 bb = *(const float4*)(b_fc1 + col);
            float4 o;
            o.x = fmaxf(acc[r][0] + bb.x, 0.f);
            o.y = fmaxf(acc[r][1] + bb.y, 0.f);
            o.z = fmaxf(acc[r][2] + bb.z, 0.f);
            o.w = fmaxf(acc[r][3] + bb.w, 0.f);
            *(float4*)(g_x7 + (long)row * OUTD + col) = o;
        } else {
            float4 o = make_float4(acc[r][0], acc[r][1], acc[r][2], acc[r][3]);
            *(float4*)(g_xc2 + (long)row * OUTD + (col - 128)) = o;
        }
    }
}

// ---------------- Aggregate conv2: x7 += relu(dis[i]*sum + b_conv2) ----------------
__global__ __launch_bounds__(128) void agg2_kernel(const float* __restrict__ b_conv2, int n) {
    int i = blockIdx.x;
    if (i >= n) return;
    int f = threadIdx.x;                 // 128
    int s = g_colptr[i], e = g_colptr[i + 1];
    float acc = 0.f;
    for (int p = s; p < e; p++) {
        int r   = g_erow[p];
        float w = g_ewt[p];
        acc += w * g_xc2[(long)r * OUTD + f];
    }
    float v = fmaxf(acc * g_dis[i] + b_conv2[f], 0.f);
    g_x7[(long)i * OUTD + f] += v;
}

// ---------------- Head: per-node dots with w_fc2 / w_conv3 (warp per node) ----------------
__global__ __launch_bounds__(256) void head_kernel(
    const float* __restrict__ w_fc2, const float* __restrict__ b_fc2,
    const float* __restrict__ w_conv3, int n)
{
    int gw = (blockIdx.x * blockDim.x + threadIdx.x) >> 5;
    int lane = threadIdx.x & 31;
    if (gw >= n) return;
    float4 v  = ((const float4*)g_x7)[(long)gw * 32 + lane];
    float4 wf = ((const float4*)w_fc2)[lane];
    float4 wc = ((const float4*)w_conv3)[lane];
    float d1 = v.x * wf.x + v.y * wf.y + v.z * wf.z + v.w * wf.w;
    float d2 = v.x * wc.x + v.y * wc.y + v.z * wc.z + v.w * wc.w;
    #pragma unroll
    for (int off = 16; off > 0; off >>= 1) {
        d1 += __shfl_down_sync(0xffffffffu, d1, off);
        d2 += __shfl_down_sync(0xffffffffu, d2, off);
    }
    if (lane == 0) {
        g_pre[gw] = d1 + b_fc2[0];
        g_xc3[gw] = d2;
    }
}

// ---------------- Final aggregate conv3 + output ----------------
__global__ __launch_bounds__(256) void agg3_kernel(
    const float* __restrict__ b_conv3, float* __restrict__ out, int n)
{
    int gw = (blockIdx.x * blockDim.x + threadIdx.x) >> 5;
    int lane = threadIdx.x & 31;
    if (gw >= n) return;
    int s = g_colptr[gw], e = g_colptr[gw + 1];
    float acc = 0.f;
    for (int p = s + lane; p < e; p += 32)
        acc += g_ewt[p] * g_xc3[g_erow[p]];
    #pragma unroll
    for (int off = 16; off > 0; off >>= 1)
        acc += __shfl_down_sync(0xffffffffu, acc, off);
    if (lane == 0)
        out[gw] = g_pre[gw] + b_conv3[0] + g_dis[gw] * acc;
}

// ---------------- launch ----------------
extern "C" void kernel_launch(void* const* d_in, const int* in_sizes, int n_in,
                              void* d_out, int out_size)
{
    const float* x        = (const float*)d_in[0];
    const void*  edges    = d_in[1];
    const float* w_fc     = (const float*)d_in[2];
    const float* b_fc     = (const float*)d_in[3];
    const float* w_conv1  = (const float*)d_in[4];
    const float* b_conv1  = (const float*)d_in[5];
    const float* w_fc1    = (const float*)d_in[6];
    const float* b_fc1    = (const float*)d_in[7];
    const float* w_conv2  = (const float*)d_in[8];
    const float* b_conv2  = (const float*)d_in[9];
    const float* w_fc2    = (const float*)d_in[10];
    const float* b_fc2    = (const float*)d_in[11];
    const float* w_conv3  = (const float*)d_in[12];
    const float* b_conv3  = (const float*)d_in[13];
    float* out = (float*)d_out;

    int n = in_sizes[0] / INDIM;   // 50000
    int E = in_sizes[1] / 2;       // 800000

    int NB = (n + SCB - 1) / SCB;

    detect_kernel<<<1, 256>>>((const int*)edges, 4096);
    zero_deg_kernel<<<(n + 255) / 256, 256>>>(n);
    count_kernel<<<(E + 255) / 256, 256>>>(edges, E);
    scan_blocks_kernel<<<NB, SCB>>>(n);
    scan_sums_kernel<<<1, 1024>>>(NB);
    scan_add_kernel<<<NB, SCB>>>(n, E);
    dis_kernel<<<(n + 255) / 256, 256>>>(n);
    fill_kernel<<<(E + 255) / 256, 256>>>(edges, E);

    dim3 g1((n + 127) / 128, 8);
    gemm1_kernel<<<g1, 256>>>(x, w_fc, b_fc, w_conv1, n);
    agg1_kernel<<<n, 256>>>(b_conv1, n);

    dim3 g2((n + 127) / 128, 4);
    gemm2_kernel<<<g2, 256>>>(w_fc1, b_fc1, w_conv2, n);
    agg2_kernel<<<n, 128>>>(b_conv2, n);

    int warps = n;
    int blocks = (warps * 32 + 255) / 256;
    head_kernel<<<blocks, 256>>>(w_fc2, b_fc2, w_conv3, n);
    agg3_kernel<<<blocks, 256>>>(b_conv3, out, n);
}